// round 9
// baseline (speedup 1.0000x reference)
#include <cuda_runtime.h>
#include <cuda_fp16.h>
#include <cstdint>

#define HIDDEN 1024
#define FFNDIM 4096
#define NEXP 8
#define MAXTOK 16384
#define BMT 128                     // CTA M tile
#define BNT 128                     // CTA N tile
#define BK 64                       // k-chunk (fp16 elems) = 128B A rows
#define PAD_ROWS (2*MAXTOK + NEXP*BMT)    // 33792
#define MTILES (PAD_ROWS/BMT)             // 264
#define STAGE_BYTES 32768           // A 16KB + B 16KB
#define NSTAGE 3
#define SMEM_BYTES (NSTAGE*STAGE_BYTES)   // 98304

// swizzles: XOR 16B-chunk bits[6:4] with row&7
#define SWA(b) ((b) ^ (((b) >> 3) & 0x70))   // A: 128B rows  (bits[9:7] = row&7)
#define SWB(b) ((b) ^ (((b) >> 4) & 0x70))   // B: 256B rows  (bits[10:8] = row&7)

// ---------------- device scratch (static; no runtime allocation) ----------------
__device__ __half g_W1h[(size_t)NEXP * HIDDEN * FFNDIM];  // [E][K][N] fp16
__device__ __half g_W2h[(size_t)NEXP * FFNDIM * HIDDEN];  // [E][K][N] fp16
__device__ __half g_Xh[(size_t)MAXTOK * HIDDEN];          // fp16 x (written by gate)
__device__ __half g_Hh[(size_t)PAD_ROWS * FFNDIM];        // GEMM1 out fp16
__device__ __half g_Yh[(size_t)PAD_ROWS * HIDDEN];        // GEMM2 out fp16
__device__ int    g_tok[PAD_ROWS];
__device__ int    g_slotOf[MAXTOK * 2];
__device__ int    g_te[MAXTOK * 2];
__device__ float  g_tw[MAXTOK * 2];
__device__ int    g_cnt[NEXP];
__device__ int    g_base[NEXP + 1];

// ---------------- PTX helpers ----------------
__device__ __forceinline__ void cp16(uint32_t dst, const void* src, int bytes) {
    asm volatile("cp.async.cg.shared.global [%0], [%1], 16, %2;"
                 :: "r"(dst), "l"(src), "r"(bytes));
}
__device__ __forceinline__ void cp_commit() { asm volatile("cp.async.commit_group;"); }
template <int N>
__device__ __forceinline__ void cp_wait() { asm volatile("cp.async.wait_group %0;" :: "n"(N)); }

__device__ __forceinline__ void ldsm4(uint32_t* r, uint32_t addr) {
    asm volatile("ldmatrix.sync.aligned.m8n8.x4.shared.b16 {%0,%1,%2,%3}, [%4];"
                 : "=r"(r[0]), "=r"(r[1]), "=r"(r[2]), "=r"(r[3]) : "r"(addr));
}
__device__ __forceinline__ void ldsm4t(uint32_t* r, uint32_t addr) {
    asm volatile("ldmatrix.sync.aligned.m8n8.x4.trans.shared.b16 {%0,%1,%2,%3}, [%4];"
                 : "=r"(r[0]), "=r"(r[1]), "=r"(r[2]), "=r"(r[3]) : "r"(addr));
}
__device__ __forceinline__ void mma16(float* c, const uint32_t* a, const uint32_t* b) {
    asm volatile(
        "mma.sync.aligned.m16n8k16.row.col.f32.f16.f16.f32 "
        "{%0,%1,%2,%3},{%4,%5,%6,%7},{%8,%9},{%0,%1,%2,%3};"
        : "+f"(c[0]), "+f"(c[1]), "+f"(c[2]), "+f"(c[3])
        : "r"(a[0]), "r"(a[1]), "r"(a[2]), "r"(a[3]), "r"(b[0]), "r"(b[1]));
}

// ---------------- 1: merged prep: cvt W1 | cvt W2 | gate(+x->fp16, counters) --
// Block ranges:  [0, WB)            -> W1 fp32->fp16
//                [WB, 2*WB)         -> W2 fp32->fp16
//                [2*WB, 2*WB+GB)    -> gating (one warp per token)
#define WBLK ((NEXP * HIDDEN * FFNDIM / 2 + 255) / 256)   // 65536
__global__ void prep_kernel(const float* __restrict__ W1, const float* __restrict__ W2,
                            const float* __restrict__ x, const float* __restrict__ Wg,
                            const float* __restrict__ bg, int ntok) {
    int b = blockIdx.x;
    if (b == 0 && threadIdx.x < NEXP) g_cnt[threadIdx.x] = 0;   // reset (pre-gate, same kernel:
                                                                 // gate atomics come later in
                                                                 // other blocks only after their
                                                                 // own work; ordering enforced by
                                                                 // doing reset in block 0 AND
                                                                 // gate blocks using atomicAdd on
                                                                 // values reset at launch start)
    if (b < WBLK) {
        int i = b * 256 + threadIdx.x;
        float2 v = reinterpret_cast<const float2*>(W1)[i];
        reinterpret_cast<__half2*>(g_W1h)[i] = __floats2half2_rn(v.x, v.y);
        return;
    }
    b -= WBLK;
    if (b < WBLK) {
        int i = b * 256 + threadIdx.x;
        float2 v = reinterpret_cast<const float2*>(W2)[i];
        reinterpret_cast<__half2*>(g_W2h)[i] = __floats2half2_rn(v.x, v.y);
        return;
    }
    b -= WBLK;
    // ---- gating: 8 warps per block, one token per warp ----
    int gwarp = (b * 256 + (int)threadIdx.x) >> 5;
    int lane = threadIdx.x & 31;
    if (gwarp >= ntok) return;
    const float* xr = x + (size_t)gwarp * HIDDEN;
    __half* xh = g_Xh + (size_t)gwarp * HIDDEN;

    double s[NEXP];
#pragma unroll
    for (int e = 0; e < NEXP; e++) s[e] = 0.0;
    for (int k = lane; k < HIDDEN; k += 32) {
        float xv = xr[k];
        xh[k] = __float2half_rn(xv);
        double xd = (double)xv;
        const float* wr = Wg + (size_t)k * NEXP;
#pragma unroll
        for (int e = 0; e < NEXP; e++) s[e] += xd * (double)wr[e];
    }
#pragma unroll
    for (int off = 16; off > 0; off >>= 1)
#pragma unroll
        for (int e = 0; e < NEXP; e++) s[e] += __shfl_down_sync(0xffffffffu, s[e], off);

    if (lane == 0) {
        double best = -1e300, sec = -1e300;
        int bi = 0, si = 0;
#pragma unroll
        for (int e = 0; e < NEXP; e++) {
            double v = s[e] + (double)bg[e];
            if (v > best) { sec = best; si = bi; best = v; bi = e; }
            else if (v > sec) { sec = v; si = e; }
        }
        double t = exp(sec - best);
        double w2 = t / (1.0 + t);
        g_te[2 * gwarp] = bi;
        g_te[2 * gwarp + 1] = si;
        g_tw[2 * gwarp] = (float)(1.0 - w2);
        g_tw[2 * gwarp + 1] = (float)w2;
        atomicAdd(&g_cnt[bi], 1);
        atomicAdd(&g_cnt[si], 1);
    }
}

// ---------------- 2: scan + scatter (single block, smem atomics) --------------
__global__ void scanscatter_kernel(int ntok) {
    __shared__ int s_base[NEXP];
    __shared__ int s_cur[NEXP];
    int tid = threadIdx.x;
    if (tid == 0) {
        int run = 0;
        for (int e = 0; e < NEXP; e++) {
            s_base[e] = run;
            g_base[e] = run;
            run += ((g_cnt[e] + BMT - 1) / BMT) * BMT;
        }
        g_base[NEXP] = run;
    }
    if (tid < NEXP) s_cur[tid] = 0;
    __syncthreads();
    for (int t = tid; t < ntok; t += blockDim.x) {
#pragma unroll
        for (int j = 0; j < 2; j++) {
            int e = g_te[2 * t + j];
            int p = atomicAdd(&s_cur[e], 1);
            int slot = s_base[e] + p;
            g_tok[slot] = t;
            g_slotOf[2 * t + j] = slot;
        }
    }
}

// ---------------- 3/4: grouped fp16 GEMM (R7 config: 256 thr, 64x32 tiles) ----
// MODE 0: g_Hh[slot] = fp16(relu(Xh[tok(slot)] @ W1h_e + b1_e))   K=1024 N=4096
// MODE 1: g_Yh[slot] = fp16(g_Hh[slot] @ W2h_e + b2_e)             K=4096 N=1024
template <int MODE, int KDIM, int NDIM>
__global__ __launch_bounds__(256, 2) void moe_gemm_f16(const __half* __restrict__ Ag,
                                                       const __half* __restrict__ Wh,
                                                       const float* __restrict__ bias) {
    extern __shared__ char smem[];
    __shared__ int stok[BMT];
    const uint32_t sbase = (uint32_t)__cvta_generic_to_shared(smem);

    const int tid = threadIdx.x;
    const int wid = tid >> 5;
    const int lane = tid & 31;
    const int n0 = blockIdx.x * BNT;
    const int row0 = blockIdx.y * BMT;

    const int total = g_base[NEXP];
    if (row0 >= total) return;
    int e = 0;
    while (row0 >= g_base[e + 1]) e++;
    const int send = g_base[e] + g_cnt[e];

    const __half* We = Wh + (size_t)e * KDIM * NDIM;
    const __half* Ap = (MODE == 0) ? Ag : (const __half*)g_Hh;

    if (MODE == 0 && tid < BMT) {
        int slot = row0 + tid;
        stok[tid] = (slot < send) ? g_tok[slot] : 0x7fffffff;
    }
    __syncthreads();

    // ---- producer: one BK=64 chunk -> A 128x64 (16KB, SWA) + B 64x128 (16KB, SWB)
    auto fill = [&](int c) {
        const int k0 = c * BK;
        const uint32_t abuf = sbase + (c % NSTAGE) * STAGE_BYTES;
        const uint32_t bbuf = abuf + 16384;
#pragma unroll
        for (int i = 0; i < 4; i++) {      // A: 1024 16B-chunks
            int idx = tid + i * 256;
            int r = idx >> 3;              // row 0..127
            int ck = idx & 7;              // 16B chunk (8 halves)
            uint32_t b = (uint32_t)(r * 128 + ck * 16);
            const __half* src;
            int bytes = 16;
            if (MODE == 0) {
                int tok = stok[r];
                if (tok == 0x7fffffff) { bytes = 0; tok = 0; }
                src = Ap + (size_t)tok * KDIM + k0 + ck * 8;
            } else {
                src = Ap + (size_t)(row0 + r) * KDIM + k0 + ck * 8;
            }
            cp16(abuf + SWA(b), src, bytes);
        }
#pragma unroll
        for (int i = 0; i < 4; i++) {      // B: 1024 16B-chunks
            int idx = tid + i * 256;
            int k = idx >> 4;              // k-row 0..63
            int cn = idx & 15;             // 16B chunk along n
            uint32_t b = (uint32_t)(k * 256 + cn * 16);
            const __half* src = We + (size_t)(k0 + k) * NDIM + n0 + cn * 8;
            cp16(bbuf + SWB(b), src, 16);
        }
    };

    // 8 warps: 2(m) x 4(n) grid of 64x32 warp tiles
    const int wm = (wid >> 2) * 64;
    const int wn = (wid & 3) * 32;

    float acc[4][4][4];
#pragma unroll
    for (int mi = 0; mi < 4; mi++)
#pragma unroll
        for (int nj = 0; nj < 4; nj++)
#pragma unroll
            for (int q = 0; q < 4; q++) acc[mi][nj][q] = 0.f;

    const int KT = KDIM / BK;
    fill(0); cp_commit();
    fill(1); cp_commit();

    for (int c = 0; c < KT; c++) {
        if (c + 1 < KT) cp_wait<1>(); else cp_wait<0>();
        __syncthreads();
        const uint32_t abuf = sbase + (c % NSTAGE) * STAGE_BYTES;
        const uint32_t bbuf = abuf + 16384;
#pragma unroll
        for (int ks = 0; ks < 4; ks++) {   // 4 x k16 per chunk
            uint32_t af[4][4], bf[2][4];
#pragma unroll
            for (int mi = 0; mi < 4; mi++) {
                int row = wm + mi * 16 + (lane & 15);
                uint32_t b = (uint32_t)(row * 128 + (ks * 16 + (lane >> 4) * 8) * 2);
                ldsm4(af[mi], abuf + SWA(b));
            }
#pragma unroll
            for (int nt = 0; nt < 2; nt++) {
                int k = ks * 16 + (lane & 15);
                int n = wn + nt * 16 + (lane >> 4) * 8;
                uint32_t b = (uint32_t)(k * 256 + n * 2);
                ldsm4t(bf[nt], bbuf + SWB(b));
            }
#pragma unroll
            for (int mi = 0; mi < 4; mi++)
#pragma unroll
                for (int nj = 0; nj < 4; nj++)
                    mma16(acc[mi][nj], af[mi], &bf[nj >> 1][(nj & 1) * 2]);
        }
        if (c + 2 < KT) { fill(c + 2); cp_commit(); }
        // no trailing __syncthreads: stages c/c+1/c+2 distinct mod 3; barrier tops each iter
    }

    // ---- epilogue ----
    const float* be = bias + (size_t)e * NDIM;
#pragma unroll
    for (int mi = 0; mi < 4; mi++) {
        int r0 = row0 + wm + mi * 16 + (lane >> 2);
        int r1 = r0 + 8;
        bool v0 = r0 < send, v1 = r1 < send;
#pragma unroll
        for (int nj = 0; nj < 4; nj++) {
            int col = wn + nj * 8 + (lane & 3) * 2;
            float b0 = be[n0 + col], b1 = be[n0 + col + 1];
            if (MODE == 0) {
                if (v0) {
                    __half2 h = __floats2half2_rn(fmaxf(acc[mi][nj][0] + b0, 0.f),
                                                  fmaxf(acc[mi][nj][1] + b1, 0.f));
                    *reinterpret_cast<__half2*>(&g_Hh[(size_t)r0 * FFNDIM + n0 + col]) = h;
                }
                if (v1) {
                    __half2 h = __floats2half2_rn(fmaxf(acc[mi][nj][2] + b0, 0.f),
                                                  fmaxf(acc[mi][nj][3] + b1, 0.f));
                    *reinterpret_cast<__half2*>(&g_Hh[(size_t)r1 * FFNDIM + n0 + col]) = h;
                }
            } else {
                if (v0) {
                    __half2 h = __floats2half2_rn(acc[mi][nj][0] + b0, acc[mi][nj][1] + b1);
                    *reinterpret_cast<__half2*>(&g_Yh[(size_t)r0 * HIDDEN + n0 + col]) = h;
                }
                if (v1) {
                    __half2 h = __floats2half2_rn(acc[mi][nj][2] + b0, acc[mi][nj][3] + b1);
                    *reinterpret_cast<__half2*>(&g_Yh[(size_t)r1 * HIDDEN + n0 + col]) = h;
                }
            }
        }
    }
}

// ---------------- 5: combine (out[t] = w0*Y[slot0] + w1*Y[slot1]) -------------
__global__ void combine_kernel(float* __restrict__ out) {
    int t = blockIdx.x;
    int c = threadIdx.x;  // 256 threads -> 1024 cols (4 halves/thread)
    int s0 = g_slotOf[2 * t], s1 = g_slotOf[2 * t + 1];
    float w0 = g_tw[2 * t], w1 = g_tw[2 * t + 1];
    uint2 au = *reinterpret_cast<const uint2*>(g_Yh + (size_t)s0 * HIDDEN + c * 4);
    uint2 bu = *reinterpret_cast<const uint2*>(g_Yh + (size_t)s1 * HIDDEN + c * 4);
    float2 a0 = __half22float2(*reinterpret_cast<__half2*>(&au.x));
    float2 a1 = __half22float2(*reinterpret_cast<__half2*>(&au.y));
    float2 b0 = __half22float2(*reinterpret_cast<__half2*>(&bu.x));
    float2 b1 = __half22float2(*reinterpret_cast<__half2*>(&bu.y));
    float4 v;
    v.x = w0 * a0.x + w1 * b0.x;
    v.y = w0 * a0.y + w1 * b0.y;
    v.z = w0 * a1.x + w1 * b1.x;
    v.w = w0 * a1.y + w1 * b1.y;
    *reinterpret_cast<float4*>(out + (size_t)t * HIDDEN + c * 4) = v;
}

// ---------------- launcher (5 launches; gemm2 is #4 = ncu capture slot) -------
extern "C" void kernel_launch(void* const* d_in, const int* in_sizes, int n_in,
                              void* d_out, int out_size) {
    const float* x  = (const float*)d_in[0];
    const float* Wg = (const float*)d_in[1];
    const float* bg = (const float*)d_in[2];
    const float* W1 = (const float*)d_in[3];
    const float* b1 = (const float*)d_in[4];
    const float* W2 = (const float*)d_in[5];
    const float* b2 = (const float*)d_in[6];
    float* out = (float*)d_out;
    const int ntok = in_sizes[0] / HIDDEN;

    cudaFuncSetAttribute(moe_gemm_f16<0, HIDDEN, FFNDIM>,
                         cudaFuncAttributeMaxDynamicSharedMemorySize, SMEM_BYTES);
    cudaFuncSetAttribute(moe_gemm_f16<1, FFNDIM, HIDDEN>,
                         cudaFuncAttributeMaxDynamicSharedMemorySize, SMEM_BYTES);

    __half* w2h; cudaGetSymbolAddress((void**)&w2h, g_W2h);
    __half* w1h; cudaGetSymbolAddress((void**)&w1h, g_W1h);
    __half* xh;  cudaGetSymbolAddress((void**)&xh, g_Xh);

    int gateBlocks = (ntok * 32 + 255) / 256;
    int totalBlocks = 2 * WBLK + gateBlocks;

    prep_kernel<<<totalBlocks, 256>>>(W1, W2, x, Wg, bg, ntok);            // 1
    scanscatter_kernel<<<1, 1024>>>(ntok);                                 // 2
    moe_gemm_f16<0, HIDDEN, FFNDIM><<<dim3(FFNDIM / BNT, MTILES), 256, SMEM_BYTES>>>(xh, w1h, b1);  // 3
    moe_gemm_f16<1, FFNDIM, HIDDEN><<<dim3(HIDDEN / BNT, MTILES), 256, SMEM_BYTES>>>(nullptr, w2h, b2);  // 4 <- ncu
    combine_kernel<<<ntok, 256>>>(out);                                    // 5
}

// round 10
// speedup vs baseline: 1.0192x; 1.0192x over previous
#include <cuda_runtime.h>
#include <cuda_fp16.h>
#include <cstdint>

#define HIDDEN 1024
#define FFNDIM 4096
#define NEXP 8
#define MAXTOK 16384
#define BMT 128                     // CTA M tile
#define BNT 128                     // CTA N tile
#define BK 64                       // k-chunk (fp16 elems) = 128B A rows
#define PAD_ROWS (2*MAXTOK + NEXP*BMT)    // 33792
#define MTILES (PAD_ROWS/BMT)             // 264
#define CVT_BLKS_Y 32               // extra grid rows in gemm1 doing W2 cvt
#define STAGE_BYTES 32768           // A 16KB + B 16KB
#define NSTAGE 3
#define SMEM_BYTES (NSTAGE*STAGE_BYTES)   // 98304

// swizzles: XOR 16B-chunk bits[6:4] with row&7
#define SWA(b) ((b) ^ (((b) >> 3) & 0x70))   // A: 128B rows  (bits[9:7] = row&7)
#define SWB(b) ((b) ^ (((b) >> 4) & 0x70))   // B: 256B rows  (bits[10:8] = row&7)

// ---------------- device scratch (static; no runtime allocation) ----------------
__device__ __half g_W1h[(size_t)NEXP * HIDDEN * FFNDIM];  // [E][K][N] fp16
__device__ __half g_W2h[(size_t)NEXP * FFNDIM * HIDDEN];  // [E][K][N] fp16
__device__ __half g_Xh[(size_t)MAXTOK * HIDDEN];          // fp16 x (written by gate)
__device__ __half g_Hh[(size_t)PAD_ROWS * FFNDIM];        // GEMM1 out fp16
__device__ __half g_Yh[(size_t)PAD_ROWS * HIDDEN];        // GEMM2 out fp16
__device__ int    g_tok[PAD_ROWS];
__device__ int    g_slotOf[MAXTOK * 2];
__device__ int    g_te[MAXTOK * 2];
__device__ float  g_tw[MAXTOK * 2];
__device__ int    g_cnt[NEXP];
__device__ int    g_base[NEXP + 1];

// ---------------- PTX helpers ----------------
__device__ __forceinline__ void cp16(uint32_t dst, const void* src, int bytes) {
    asm volatile("cp.async.cg.shared.global [%0], [%1], 16, %2;"
                 :: "r"(dst), "l"(src), "r"(bytes));
}
__device__ __forceinline__ void cp_commit() { asm volatile("cp.async.commit_group;"); }
template <int N>
__device__ __forceinline__ void cp_wait() { asm volatile("cp.async.wait_group %0;" :: "n"(N)); }

__device__ __forceinline__ void ldsm4(uint32_t* r, uint32_t addr) {
    asm volatile("ldmatrix.sync.aligned.m8n8.x4.shared.b16 {%0,%1,%2,%3}, [%4];"
                 : "=r"(r[0]), "=r"(r[1]), "=r"(r[2]), "=r"(r[3]) : "r"(addr));
}
__device__ __forceinline__ void ldsm4t(uint32_t* r, uint32_t addr) {
    asm volatile("ldmatrix.sync.aligned.m8n8.x4.trans.shared.b16 {%0,%1,%2,%3}, [%4];"
                 : "=r"(r[0]), "=r"(r[1]), "=r"(r[2]), "=r"(r[3]) : "r"(addr));
}
__device__ __forceinline__ void mma16(float* c, const uint32_t* a, const uint32_t* b) {
    asm volatile(
        "mma.sync.aligned.m16n8k16.row.col.f32.f16.f16.f32 "
        "{%0,%1,%2,%3},{%4,%5,%6,%7},{%8,%9},{%0,%1,%2,%3};"
        : "+f"(c[0]), "+f"(c[1]), "+f"(c[2]), "+f"(c[3])
        : "r"(a[0]), "r"(a[1]), "r"(a[2]), "r"(a[3]), "r"(b[0]), "r"(b[1]));
}

// ---------------- 1: W1 convert + counter reset (merged) ----------------
__global__ void cvtW1_reset_kernel(const float* __restrict__ src, int n2) {
    if (blockIdx.x == 0 && threadIdx.x < NEXP) g_cnt[threadIdx.x] = 0;
    int i = blockIdx.x * blockDim.x + threadIdx.x;
    if (i >= n2) return;
    float2 v = reinterpret_cast<const float2*>(src)[i];
    reinterpret_cast<__half2*>(g_W1h)[i] = __floats2half2_rn(v.x, v.y);
}

// ---------------- 2: gating (one warp per token, fp64 accumulate) + x->fp16 ---
__global__ void gate_kernel(const float* __restrict__ x, const float* __restrict__ Wg,
                            const float* __restrict__ bg, int ntok) {
    int gwarp = (blockIdx.x * blockDim.x + threadIdx.x) >> 5;
    int lane = threadIdx.x & 31;
    if (gwarp >= ntok) return;
    const float* xr = x + (size_t)gwarp * HIDDEN;
    __half* xh = g_Xh + (size_t)gwarp * HIDDEN;

    double s[NEXP];
#pragma unroll
    for (int e = 0; e < NEXP; e++) s[e] = 0.0;
    for (int k = lane; k < HIDDEN; k += 32) {
        float xv = xr[k];
        xh[k] = __float2half_rn(xv);
        double xd = (double)xv;
        const float* wr = Wg + (size_t)k * NEXP;
#pragma unroll
        for (int e = 0; e < NEXP; e++) s[e] += xd * (double)wr[e];
    }
#pragma unroll
    for (int off = 16; off > 0; off >>= 1)
#pragma unroll
        for (int e = 0; e < NEXP; e++) s[e] += __shfl_down_sync(0xffffffffu, s[e], off);

    if (lane == 0) {
        double best = -1e300, sec = -1e300;
        int bi = 0, si = 0;
#pragma unroll
        for (int e = 0; e < NEXP; e++) {
            double v = s[e] + (double)bg[e];
            if (v > best) { sec = best; si = bi; best = v; bi = e; }
            else if (v > sec) { sec = v; si = e; }
        }
        double t = exp(sec - best);
        double w2 = t / (1.0 + t);
        g_te[2 * gwarp] = bi;
        g_te[2 * gwarp + 1] = si;
        g_tw[2 * gwarp] = (float)(1.0 - w2);
        g_tw[2 * gwarp + 1] = (float)w2;
        atomicAdd(&g_cnt[bi], 1);
        atomicAdd(&g_cnt[si], 1);
    }
}

// ---------------- 3: scan + scatter (single block, smem atomics) --------------
__global__ void scanscatter_kernel(int ntok) {
    __shared__ int s_base[NEXP];
    __shared__ int s_cur[NEXP];
    int tid = threadIdx.x;
    if (tid == 0) {
        int run = 0;
        for (int e = 0; e < NEXP; e++) {
            s_base[e] = run;
            g_base[e] = run;
            run += ((g_cnt[e] + BMT - 1) / BMT) * BMT;
        }
        g_base[NEXP] = run;
    }
    if (tid < NEXP) s_cur[tid] = 0;
    __syncthreads();
    for (int t = tid; t < ntok; t += blockDim.x) {
#pragma unroll
        for (int j = 0; j < 2; j++) {
            int e = g_te[2 * t + j];
            int p = atomicAdd(&s_cur[e], 1);
            int slot = s_base[e] + p;
            g_tok[slot] = t;
            g_slotOf[2 * t + j] = slot;
        }
    }
}

// ---------------- 4/5: grouped fp16 GEMM (256 thr, 64x32 tiles, 2 CTA/SM) -----
// MODE 0: g_Hh[slot] = fp16(relu(Xh[tok(slot)] @ W1h_e + b1_e))   K=1024 N=4096
//         + extra grid rows (y >= MTILES) convert W2 fp32->fp16 (tail overlap)
// MODE 1: g_Yh[slot] = fp16(g_Hh[slot] @ W2h_e + b2_e)             K=4096 N=1024
template <int MODE, int KDIM, int NDIM>
__global__ __launch_bounds__(256, 2) void moe_gemm_f16(const __half* __restrict__ Ag,
                                                       const __half* __restrict__ Wh,
                                                       const float* __restrict__ bias,
                                                       const float* __restrict__ W2src) {
    // ---- fused W2-cvt blocks (GEMM1 only): run in GEMM1's tail waves ----
    if (MODE == 0 && blockIdx.y >= MTILES) {
        int bid = (blockIdx.y - MTILES) * 32 + blockIdx.x;   // 0..1023
        const float2* src = reinterpret_cast<const float2*>(W2src);
        __half2* dst = reinterpret_cast<__half2*>(g_W2h);
        int base = bid * (256 * 64) + (int)threadIdx.x;
#pragma unroll 4
        for (int j = 0; j < 64; j++) {
            float2 v = src[base + j * 256];
            dst[base + j * 256] = __floats2half2_rn(v.x, v.y);
        }
        return;
    }

    extern __shared__ char smem[];
    __shared__ int stok[BMT];
    const uint32_t sbase = (uint32_t)__cvta_generic_to_shared(smem);

    const int tid = threadIdx.x;
    const int wid = tid >> 5;
    const int lane = tid & 31;
    const int n0 = blockIdx.x * BNT;
    const int row0 = blockIdx.y * BMT;

    const int total = g_base[NEXP];
    if (row0 >= total) return;
    int e = 0;
    while (row0 >= g_base[e + 1]) e++;
    const int send = g_base[e] + g_cnt[e];

    const __half* We = Wh + (size_t)e * KDIM * NDIM;
    const __half* Ap = (MODE == 0) ? Ag : (const __half*)g_Hh;

    if (MODE == 0 && tid < BMT) {
        int slot = row0 + tid;
        stok[tid] = (slot < send) ? g_tok[slot] : 0x7fffffff;
    }
    __syncthreads();

    // ---- producer: one BK=64 chunk -> A 128x64 (16KB, SWA) + B 64x128 (16KB, SWB)
    auto fill = [&](int c) {
        const int k0 = c * BK;
        const uint32_t abuf = sbase + (c % NSTAGE) * STAGE_BYTES;
        const uint32_t bbuf = abuf + 16384;
#pragma unroll
        for (int i = 0; i < 4; i++) {      // A: 1024 16B-chunks
            int idx = tid + i * 256;
            int r = idx >> 3;              // row 0..127
            int ck = idx & 7;              // 16B chunk (8 halves)
            uint32_t b = (uint32_t)(r * 128 + ck * 16);
            const __half* src;
            int bytes = 16;
            if (MODE == 0) {
                int tok = stok[r];
                if (tok == 0x7fffffff) { bytes = 0; tok = 0; }
                src = Ap + (size_t)tok * KDIM + k0 + ck * 8;
            } else {
                src = Ap + (size_t)(row0 + r) * KDIM + k0 + ck * 8;
            }
            cp16(abuf + SWA(b), src, bytes);
        }
#pragma unroll
        for (int i = 0; i < 4; i++) {      // B: 1024 16B-chunks
            int idx = tid + i * 256;
            int k = idx >> 4;              // k-row 0..63
            int cn = idx & 15;             // 16B chunk along n
            uint32_t b = (uint32_t)(k * 256 + cn * 16);
            const __half* src = We + (size_t)(k0 + k) * NDIM + n0 + cn * 8;
            cp16(bbuf + SWB(b), src, 16);
        }
    };

    // 8 warps: 2(m) x 4(n) grid of 64x32 warp tiles
    const int wm = (wid >> 2) * 64;
    const int wn = (wid & 3) * 32;

    float acc[4][4][4];
#pragma unroll
    for (int mi = 0; mi < 4; mi++)
#pragma unroll
        for (int nj = 0; nj < 4; nj++)
#pragma unroll
            for (int q = 0; q < 4; q++) acc[mi][nj][q] = 0.f;

    const int KT = KDIM / BK;
    fill(0); cp_commit();
    fill(1); cp_commit();

    for (int c = 0; c < KT; c++) {
        if (c + 1 < KT) cp_wait<1>(); else cp_wait<0>();
        __syncthreads();
        const uint32_t abuf = sbase + (c % NSTAGE) * STAGE_BYTES;
        const uint32_t bbuf = abuf + 16384;
#pragma unroll
        for (int ks = 0; ks < 4; ks++) {   // 4 x k16 per chunk
            uint32_t af[4][4], bf[2][4];
#pragma unroll
            for (int mi = 0; mi < 4; mi++) {
                int row = wm + mi * 16 + (lane & 15);
                uint32_t b = (uint32_t)(row * 128 + (ks * 16 + (lane >> 4) * 8) * 2);
                ldsm4(af[mi], abuf + SWA(b));
            }
#pragma unroll
            for (int nt = 0; nt < 2; nt++) {
                int k = ks * 16 + (lane & 15);
                int n = wn + nt * 16 + (lane >> 4) * 8;
                uint32_t b = (uint32_t)(k * 256 + n * 2);
                ldsm4t(bf[nt], bbuf + SWB(b));
            }
#pragma unroll
            for (int mi = 0; mi < 4; mi++)
#pragma unroll
                for (int nj = 0; nj < 4; nj++)
                    mma16(acc[mi][nj], af[mi], &bf[nj >> 1][(nj & 1) * 2]);
        }
        if (c + 2 < KT) { fill(c + 2); cp_commit(); }
        // no trailing __syncthreads: stages c/c+1/c+2 distinct mod 3; barrier tops each iter
    }

    // ---- epilogue ----
    const float* be = bias + (size_t)e * NDIM;
#pragma unroll
    for (int mi = 0; mi < 4; mi++) {
        int r0 = row0 + wm + mi * 16 + (lane >> 2);
        int r1 = r0 + 8;
        bool v0 = r0 < send, v1 = r1 < send;
#pragma unroll
        for (int nj = 0; nj < 4; nj++) {
            int col = wn + nj * 8 + (lane & 3) * 2;
            float b0 = be[n0 + col], b1 = be[n0 + col + 1];
            if (MODE == 0) {
                if (v0) {
                    __half2 h = __floats2half2_rn(fmaxf(acc[mi][nj][0] + b0, 0.f),
                                                  fmaxf(acc[mi][nj][1] + b1, 0.f));
                    *reinterpret_cast<__half2*>(&g_Hh[(size_t)r0 * FFNDIM + n0 + col]) = h;
                }
                if (v1) {
                    __half2 h = __floats2half2_rn(fmaxf(acc[mi][nj][2] + b0, 0.f),
                                                  fmaxf(acc[mi][nj][3] + b1, 0.f));
                    *reinterpret_cast<__half2*>(&g_Hh[(size_t)r1 * FFNDIM + n0 + col]) = h;
                }
            } else {
                if (v0) {
                    __half2 h = __floats2half2_rn(acc[mi][nj][0] + b0, acc[mi][nj][1] + b1);
                    *reinterpret_cast<__half2*>(&g_Yh[(size_t)r0 * HIDDEN + n0 + col]) = h;
                }
                if (v1) {
                    __half2 h = __floats2half2_rn(acc[mi][nj][2] + b0, acc[mi][nj][3] + b1);
                    *reinterpret_cast<__half2*>(&g_Yh[(size_t)r1 * HIDDEN + n0 + col]) = h;
                }
            }
        }
    }
}

// ---------------- 6: combine (out[t] = w0*Y[slot0] + w1*Y[slot1]) -------------
__global__ void combine_kernel(float* __restrict__ out) {
    int t = blockIdx.x;
    int c = threadIdx.x;  // 256 threads -> 1024 cols (4 halves/thread)
    int s0 = g_slotOf[2 * t], s1 = g_slotOf[2 * t + 1];
    float w0 = g_tw[2 * t], w1 = g_tw[2 * t + 1];
    uint2 au = *reinterpret_cast<const uint2*>(g_Yh + (size_t)s0 * HIDDEN + c * 4);
    uint2 bu = *reinterpret_cast<const uint2*>(g_Yh + (size_t)s1 * HIDDEN + c * 4);
    float2 a0 = __half22float2(*reinterpret_cast<__half2*>(&au.x));
    float2 a1 = __half22float2(*reinterpret_cast<__half2*>(&au.y));
    float2 b0 = __half22float2(*reinterpret_cast<__half2*>(&bu.x));
    float2 b1 = __half22float2(*reinterpret_cast<__half2*>(&bu.y));
    float4 v;
    v.x = w0 * a0.x + w1 * b0.x;
    v.y = w0 * a0.y + w1 * b0.y;
    v.z = w0 * a1.x + w1 * b1.x;
    v.w = w0 * a1.y + w1 * b1.y;
    *reinterpret_cast<float4*>(out + (size_t)t * HIDDEN + c * 4) = v;
}

// ---------------- launcher (6 launches; gemm1 is #4 = ncu capture slot) -------
extern "C" void kernel_launch(void* const* d_in, const int* in_sizes, int n_in,
                              void* d_out, int out_size) {
    const float* x  = (const float*)d_in[0];
    const float* Wg = (const float*)d_in[1];
    const float* bg = (const float*)d_in[2];
    const float* W1 = (const float*)d_in[3];
    const float* b1 = (const float*)d_in[4];
    const float* W2 = (const float*)d_in[5];
    const float* b2 = (const float*)d_in[6];
    float* out = (float*)d_out;
    const int ntok = in_sizes[0] / HIDDEN;

    cudaFuncSetAttribute(moe_gemm_f16<0, HIDDEN, FFNDIM>,
                         cudaFuncAttributeMaxDynamicSharedMemorySize, SMEM_BYTES);
    cudaFuncSetAttribute(moe_gemm_f16<1, FFNDIM, HIDDEN>,
                         cudaFuncAttributeMaxDynamicSharedMemorySize, SMEM_BYTES);

    __half* w2h; cudaGetSymbolAddress((void**)&w2h, g_W2h);
    __half* w1h; cudaGetSymbolAddress((void**)&w1h, g_W1h);
    __half* xh;  cudaGetSymbolAddress((void**)&xh, g_Xh);

    int nW = NEXP * HIDDEN * FFNDIM / 2;

    cvtW1_reset_kernel<<<(nW + 255) / 256, 256>>>(W1, nW);                 // 1
    gate_kernel<<<(ntok * 32 + 255) / 256, 256>>>(x, Wg, bg, ntok);        // 2
    scanscatter_kernel<<<1, 1024>>>(ntok);                                 // 3
    moe_gemm_f16<0, HIDDEN, FFNDIM>                                        // 4 <- ncu
        <<<dim3(FFNDIM / BNT, MTILES + CVT_BLKS_Y), 256, SMEM_BYTES>>>(xh, w1h, b1, W2);
    moe_gemm_f16<1, FFNDIM, HIDDEN>                                        // 5
        <<<dim3(HIDDEN / BNT, MTILES), 256, SMEM_BYTES>>>(nullptr, w2h, b2, nullptr);
    combine_kernel<<<ntok, 256>>>(out);                                    // 6
}